// round 13
// baseline (speedup 1.0000x reference)
#include <cuda_runtime.h>
#include <cuda_bf16.h>
#include <cstdint>
#include <cstddef>
#include <math.h>

#define NB   32      // batch
#define T1   2000
#define T2   1000
#define D1   80
#define HH   256     // hidden per direction
#define G4H  1024    // 4*H gate rows
#define HDC  512
#define OUTC 512
#define CLSZ 16      // cluster size = blocks per group (h-shards)

typedef unsigned long long ull;

// ---------------- f32x2 packed-FMA helpers (Blackwell FFMA2) -----------------
__device__ __forceinline__ void fma2(ull& d, ull a, ull b) {
    asm("fma.rn.f32x2 %0, %1, %2, %3;" : "=l"(d) : "l"(a), "l"(b), "l"(d));
}
__device__ __forceinline__ ull dup2(float x) {
    ull r; asm("mov.b64 %0, {%1, %1};" : "=l"(r) : "f"(x)); return r;
}
__device__ __forceinline__ float2 unp2(ull v) {
    float2 r; asm("mov.b64 {%0, %1}, %2;" : "=f"(r.x), "=f"(r.y) : "l"(v)); return r;
}
__device__ __forceinline__ uint32_t smem_u32(const void* p) {
    uint32_t a;
    asm("{ .reg .u64 t; cvta.to.shared.u64 t, %1; cvt.u32.u64 %0, t; }" : "=r"(a) : "l"(p));
    return a;
}
__device__ __forceinline__ uint32_t mapa_u32(uint32_t addr, int rank) {
    uint32_t r;
    asm("mapa.shared::cluster.u32 %0, %1, %2;" : "=r"(r) : "r"(addr), "r"(rank));
    return r;
}

// ---------------- device scratch ---------------------------------------------
__device__ float g_xg1f[(size_t)T1 * G4H * NB];   // [t][gate_row][b]
__device__ float g_xg1b[(size_t)T1 * G4H * NB];
__device__ float g_xg2f[(size_t)T2 * G4H * NB];
__device__ float g_xg2b[(size_t)T2 * G4H * NB];
__device__ float g_out1[(size_t)NB * T1 * HDC];   // [b][t][ch]
__device__ float g_pool1[(size_t)NB * T2 * HDC];
__device__ float g_out2[(size_t)NB * T2 * HDC];

// ---------------- small helpers ---------------------------------------------
__global__ void k_zero(float* __restrict__ p, size_t n) {
    size_t i = (size_t)blockIdx.x * blockDim.x + threadIdx.x;
    size_t st = (size_t)gridDim.x * blockDim.x;
    for (; i < n; i += st) p[i] = 0.f;
}

__global__ void k_pool(const float* __restrict__ in, float* __restrict__ out) {
    size_t n = (size_t)NB * T2 * HDC;
    size_t i = (size_t)blockIdx.x * blockDim.x + threadIdx.x;
    size_t st = (size_t)gridDim.x * blockDim.x;
    for (; i < n; i += st) {
        int c  = (int)(i % HDC);
        size_t r = i / HDC;
        int tp = (int)(r % T2);
        int b  = (int)(r / T2);
        const float* p = in + ((size_t)b * T1 + 2 * (size_t)tp) * HDC + c;
        out[i] = fmaxf(p[0], p[HDC]);
    }
}

__global__ void k_lens(const int* __restrict__ xlen, float* __restrict__ out) {
    int i = threadIdx.x;
    if (i < NB) out[i] = (float)(xlen[i] >> 1);
}

// ---------------- projection / linear GEMM (R5 version — proven 310us) -------
__global__ void __launch_bounds__(128, 2) k_proj(
    const float* __restrict__ X, const float* __restrict__ W,
    const float* __restrict__ bias, float* __restrict__ out,
    int Tt, int K, long long ot, long long orr, long long ob)
{
    __shared__ __align__(16) float a_sh[16][256];
    __shared__ __align__(16) float b_sh[16][32];

    const int t    = blockIdx.y;
    const int row0 = blockIdx.x * 256;
    const int tid  = threadIdx.x;
    const int rowg = tid >> 2;
    const int colg = tid & 3;

    ull acc[4][8];
#pragma unroll
    for (int i = 0; i < 4; i++)
#pragma unroll
        for (int j = 0; j < 8; j++) acc[i][j] = 0ull;

    for (int k0 = 0; k0 < K; k0 += 16) {
        {
            const float* wp = W + (size_t)(row0 + tid) * K + k0;
            float4 v0 = ((const float4*)wp)[0];
            float4 v1 = ((const float4*)wp)[1];
            float4 v2 = ((const float4*)wp)[2];
            float4 v3 = ((const float4*)wp)[3];
            a_sh[ 0][tid] = v0.x; a_sh[ 1][tid] = v0.y; a_sh[ 2][tid] = v0.z; a_sh[ 3][tid] = v0.w;
            a_sh[ 4][tid] = v1.x; a_sh[ 5][tid] = v1.y; a_sh[ 6][tid] = v1.z; a_sh[ 7][tid] = v1.w;
            a_sh[ 8][tid] = v2.x; a_sh[ 9][tid] = v2.y; a_sh[10][tid] = v2.z; a_sh[11][tid] = v2.w;
            a_sh[12][tid] = v3.x; a_sh[13][tid] = v3.y; a_sh[14][tid] = v3.z; a_sh[15][tid] = v3.w;
            wp += (size_t)128 * K;
            v0 = ((const float4*)wp)[0];
            v1 = ((const float4*)wp)[1];
            v2 = ((const float4*)wp)[2];
            v3 = ((const float4*)wp)[3];
            const int r2 = tid + 128;
            a_sh[ 0][r2] = v0.x; a_sh[ 1][r2] = v0.y; a_sh[ 2][r2] = v0.z; a_sh[ 3][r2] = v0.w;
            a_sh[ 4][r2] = v1.x; a_sh[ 5][r2] = v1.y; a_sh[ 6][r2] = v1.z; a_sh[ 7][r2] = v1.w;
            a_sh[ 8][r2] = v2.x; a_sh[ 9][r2] = v2.y; a_sh[10][r2] = v2.z; a_sh[11][r2] = v2.w;
            a_sh[12][r2] = v3.x; a_sh[13][r2] = v3.y; a_sh[14][r2] = v3.z; a_sh[15][r2] = v3.w;
        }
        {
            const int bb = tid >> 2, ko = (tid & 3) * 4;
            const float* xp = X + ((size_t)bb * Tt + t) * K + k0 + ko;
            float4 u = *(const float4*)xp;
            b_sh[ko + 0][bb] = u.x; b_sh[ko + 1][bb] = u.y;
            b_sh[ko + 2][bb] = u.z; b_sh[ko + 3][bb] = u.w;
        }
        __syncthreads();
#pragma unroll
        for (int kk = 0; kk < 16; kk++) {
            ulonglong2 a01 = *(const ulonglong2*)&a_sh[kk][rowg * 8];
            ulonglong2 a23 = *(const ulonglong2*)&a_sh[kk][rowg * 8 + 4];
            float4 u0 = *(const float4*)&b_sh[kk][colg * 8];
            float4 u1 = *(const float4*)&b_sh[kk][colg * 8 + 4];
            ull b0 = dup2(u0.x), b1 = dup2(u0.y), b2 = dup2(u0.z), b3 = dup2(u0.w);
            ull b4 = dup2(u1.x), b5 = dup2(u1.y), b6 = dup2(u1.z), b7 = dup2(u1.w);
            fma2(acc[0][0], a01.x, b0); fma2(acc[0][1], a01.x, b1);
            fma2(acc[0][2], a01.x, b2); fma2(acc[0][3], a01.x, b3);
            fma2(acc[0][4], a01.x, b4); fma2(acc[0][5], a01.x, b5);
            fma2(acc[0][6], a01.x, b6); fma2(acc[0][7], a01.x, b7);
            fma2(acc[1][0], a01.y, b0); fma2(acc[1][1], a01.y, b1);
            fma2(acc[1][2], a01.y, b2); fma2(acc[1][3], a01.y, b3);
            fma2(acc[1][4], a01.y, b4); fma2(acc[1][5], a01.y, b5);
            fma2(acc[1][6], a01.y, b6); fma2(acc[1][7], a01.y, b7);
            fma2(acc[2][0], a23.x, b0); fma2(acc[2][1], a23.x, b1);
            fma2(acc[2][2], a23.x, b2); fma2(acc[2][3], a23.x, b3);
            fma2(acc[2][4], a23.x, b4); fma2(acc[2][5], a23.x, b5);
            fma2(acc[2][6], a23.x, b6); fma2(acc[2][7], a23.x, b7);
            fma2(acc[3][0], a23.y, b0); fma2(acc[3][1], a23.y, b1);
            fma2(acc[3][2], a23.y, b2); fma2(acc[3][3], a23.y, b3);
            fma2(acc[3][4], a23.y, b4); fma2(acc[3][5], a23.y, b5);
            fma2(acc[3][6], a23.y, b6); fma2(acc[3][7], a23.y, b7);
        }
        __syncthreads();
    }

    const int rbase = row0 + rowg * 8;
    float4 bv0 = *(const float4*)&bias[rbase];
    float4 bv1 = *(const float4*)&bias[rbase + 4];
    const float bv[8] = {bv0.x, bv0.y, bv0.z, bv0.w, bv1.x, bv1.y, bv1.z, bv1.w};

    if (ob == 1) {
        float* op = out + (size_t)t * ot + (size_t)rbase * orr + colg * 8;
#pragma unroll
        for (int rp = 0; rp < 4; rp++) {
            float va[8], vb[8];
#pragma unroll
            for (int c = 0; c < 8; c++) {
                float2 u = unp2(acc[rp][c]);
                va[c] = u.x + bv[2 * rp];
                vb[c] = u.y + bv[2 * rp + 1];
            }
            float* r0 = op + (size_t)(2 * rp) * orr;
            float* r1 = op + (size_t)(2 * rp + 1) * orr;
            *(float4*)r0       = make_float4(va[0], va[1], va[2], va[3]);
            *(float4*)(r0 + 4) = make_float4(va[4], va[5], va[6], va[7]);
            *(float4*)r1       = make_float4(vb[0], vb[1], vb[2], vb[3]);
            *(float4*)(r1 + 4) = make_float4(vb[4], vb[5], vb[6], vb[7]);
        }
    } else {
        float* op = out + (size_t)t * ot + rbase;
#pragma unroll
        for (int c = 0; c < 8; c++) {
            size_t boff = (size_t)(colg * 8 + c) * ob;
            float2 p0 = unp2(acc[0][c]);
            float2 p1 = unp2(acc[1][c]);
            float2 p2 = unp2(acc[2][c]);
            float2 p3 = unp2(acc[3][c]);
            *(float4*)(op + boff)     = make_float4(p0.x + bv[0], p0.y + bv[1], p1.x + bv[2], p1.y + bv[3]);
            *(float4*)(op + boff + 4) = make_float4(p2.x + bv[4], p2.y + bv[5], p3.x + bv[6], p3.y + bv[7]);
        }
    }
}

// ---------------- persistent recurrent LSTM: dup'd W, packed-batch FMA2 ------
__device__ __forceinline__ float fsig(float x) {
    return 1.f / (1.f + __expf(-x));
}
__device__ __forceinline__ float ftanh(float x) {
    float e = __expf(2.f * x);
    return 1.f - 2.f / (e + 1.f);
}

// smem: w2 128KB [256 k][64 rows] ull | h_sh 16KB [2][256][8] | part [8][64][12]
#define PART_STRIDE 12
#define HBUF_FLOATS (HH * 8)
#define HBUF_BYTES  (HBUF_FLOATS * 4)
#define OFF_HSH   131072
#define OFF_PART  (OFF_HSH + 2 * HBUF_BYTES)
#define LSTM_SMEM (OFF_PART + 8 * 64 * PART_STRIDE * 4)

__global__ void __launch_bounds__(256, 1) k_lstm(
    const float* __restrict__ xgF, const float* __restrict__ xgB,
    const float* __restrict__ WhhF, const float* __restrict__ WhhB,
    const int* __restrict__ xlen, int lenShift,
    float* __restrict__ out, int Tt)
{
    extern __shared__ __align__(16) char dynsmem[];
    ull*   w2   = (ull*)dynsmem;                     // [256 k][64 rows] duplicated
    float* h_sh = (float*)(dynsmem + OFF_HSH);       // [2][256][8]
    float* part = (float*)(dynsmem + OFF_PART);      // [8][64][12]

    const int bx  = (int)blockIdx.x;
    const int dir = bx >> 6;
    const int bs  = (bx >> 4) & 3;
    const int hs  = bx & 15;           // cluster rank

    const float* xg  = dir ? xgB : xgF;
    const float* Whh = dir ? WhhB : WhhF;

    const int tid  = threadIdx.x;
    const int warp = tid >> 5, lane = tid & 31;
    const int q    = lane & 15;        // row quad (4 rows)
    const int bg4  = lane >> 4;        // batch group of 4 (0,1)
    const int kbase = warp * 32;       // 32 k per warp (8 warps)

    // ---- zero h buffers (both parities) ----
    {
        float4* hz = (float4*)h_sh;
        for (int j = tid; j < 2 * HBUF_FLOATS / 4; j += 256)
            hz[j] = make_float4(0.f, 0.f, 0.f, 0.f);
    }

    // ---- stage Whh slice [256 k][64 rows], duplicated into f32x2 lanes ----
    {
        const int r  = tid & 63;
        const int ko = (tid >> 6) * 64;    // 4 groups x 64 k
        const int grow = (r >> 4) * HH + hs * 16 + (r & 15);
        const float* wp = Whh + (size_t)grow * HH + ko;
#pragma unroll
        for (int j = 0; j < 64; j += 4) {
            float4 v = *(const float4*)(wp + j);
            w2[(size_t)(ko + j + 0) * 64 + r] = dup2(v.x);
            w2[(size_t)(ko + j + 1) * 64 + r] = dup2(v.y);
            w2[(size_t)(ko + j + 2) * 64 + r] = dup2(v.z);
            w2[(size_t)(ko + j + 3) * 64 + r] = dup2(v.w);
        }
    }

    // ---- peer DSMEM addresses for the h scatter (threads 0-127 own values) --
    const uint32_t h_u32 = smem_u32(h_sh);
    uint32_t peer[CLSZ];
#pragma unroll
    for (int r = 0; r < CLSZ; r++) peer[r] = mapa_u32(h_u32, r);
    const uint32_t selfOff = ((uint32_t)(hs * 128 + tid)) * 4u;   // valid for tid<128

    // ---- pointwise role (threads 0-127) ----
    const int hl_p = (tid >> 3) & 15;
    const int bl_p = tid & 7;
    const int hk   = hs * 16 + hl_p;
    const int b_g  = bs * 8 + bl_p;
    const int len_b = xlen[b_g] >> lenShift;
    int gmax = 0;
#pragma unroll
    for (int j = 0; j < 8; j++) {
        int l = xlen[bs * 8 + j] >> lenShift;
        gmax = (l > gmax) ? l : gmax;
    }
    float c_st = 0.f, h_st = 0.f;

    __syncthreads();
    // all CTAs' h buffers zeroed before any peer writes
    asm volatile("barrier.cluster.arrive.aligned;" ::: "memory");
    asm volatile("barrier.cluster.wait.aligned;" ::: "memory");

    // gate-input prefetch for step 0 (owner threads only)
    float xg0 = 0.f, xg1 = 0.f, xg2 = 0.f, xg3 = 0.f;
    if (tid < 128) {
        int tx = dir ? (len_b - 1) : 0;
        if (tx < 0) tx = 0;
        const float* xp = xg + (size_t)tx * (G4H * NB) + (size_t)hk * NB + b_g;
        xg0 = __ldg(xp);
        xg1 = __ldg(xp + 256 * NB);
        xg2 = __ldg(xp + 512 * NB);
        xg3 = __ldg(xp + 768 * NB);
    }

    for (int s = 0; s < gmax; s++) {
        const int bufp = s & 1;

        // ---- GEMM slice: acc[row 0..3][b-pair 0..1], 3 LDS + 8 FMA2 per k ---
        ull acc[4][2] = {};
        const ull*   wq = w2 + (size_t)kbase * 64 + q * 4;
        const float* hq = h_sh + (size_t)bufp * HBUF_FLOATS + (size_t)kbase * 8 + bg4 * 4;
#pragma unroll 16
        for (int k = 0; k < 32; k++) {
            ulonglong2 w01 = *(const ulonglong2*)(wq + (size_t)k * 64);
            ulonglong2 w23 = *(const ulonglong2*)(wq + (size_t)k * 64 + 2);
            ulonglong2 hp  = *(const ulonglong2*)(hq + (size_t)k * 8);  // (b0,b1),(b2,b3)
            fma2(acc[0][0], w01.x, hp.x); fma2(acc[0][1], w01.x, hp.y);
            fma2(acc[1][0], w01.y, hp.x); fma2(acc[1][1], w01.y, hp.y);
            fma2(acc[2][0], w23.x, hp.x); fma2(acc[2][1], w23.x, hp.y);
            fma2(acc[3][0], w23.y, hp.x); fma2(acc[3][1], w23.y, hp.y);
        }

        // ---- partials: part[warp][row(64)][b(8)] stride 12 (float4 stores) --
#pragma unroll
        for (int i = 0; i < 4; i++) {
            float2 u0 = unp2(acc[i][0]);
            float2 u1 = unp2(acc[i][1]);
            *(float4*)(part + ((size_t)warp * 64 + q * 4 + i) * PART_STRIDE + bg4 * 4) =
                make_float4(u0.x, u0.y, u1.x, u1.y);
        }
        __syncthreads();

        if (tid < 128) {
            // ---- reduce over 8 warps + pointwise for (hl_p, bl_p) ----
            float g0 = xg0, g1 = xg1, g2 = xg2, g3 = xg3;
#pragma unroll
            for (int w = 0; w < 8; w++) {
                const float* pr = part + (size_t)w * 64 * PART_STRIDE + bl_p;
                g0 += pr[(0  + hl_p) * PART_STRIDE];
                g1 += pr[(16 + hl_p) * PART_STRIDE];
                g2 += pr[(32 + hl_p) * PART_STRIDE];
                g3 += pr[(48 + hl_p) * PART_STRIDE];
            }
            float ig = fsig(g0);
            float fg = fsig(g1);
            float gg = ftanh(g2);
            float og = fsig(g3);
            float c_n = fg * c_st + ig * gg;
            float h_n = og * ftanh(c_n);
            if (s < len_b) {
                c_st = c_n; h_st = h_n;
                int t_o = dir ? (len_b - 1 - s) : s;
                out[((size_t)b_g * Tt + t_o) * HDC + dir * HH + hk] = h_n;
            }

            // ---- scatter h to all 16 CTAs' h_sh[bufp^1] via DSMEM ----
            const uint32_t off = (uint32_t)((bufp ^ 1) * HBUF_BYTES) + selfOff;
            const float hv = h_st;
#pragma unroll
            for (int r = 0; r < CLSZ; r++) {
                asm volatile("st.shared::cluster.f32 [%0], %1;"
                             :: "r"(peer[r] + off), "f"(hv) : "memory");
            }
        }

        // release my stores; overlap xg prefetch with peers finishing
        asm volatile("barrier.cluster.arrive.aligned;" ::: "memory");
        if (tid < 128) {
            int sn = s + 1;
            int tx = dir ? (len_b - 1 - sn) : sn;
            if (tx < 0) tx = 0;
            if (tx >= Tt) tx = Tt - 1;
            const float* xp = xg + (size_t)tx * (G4H * NB) + (size_t)hk * NB + b_g;
            xg0 = __ldg(xp);
            xg1 = __ldg(xp + 256 * NB);
            xg2 = __ldg(xp + 512 * NB);
            xg3 = __ldg(xp + 768 * NB);
        }
        asm volatile("barrier.cluster.wait.aligned;" ::: "memory");
    }
}

// ---------------- host orchestration ----------------------------------------
extern "C" void kernel_launch(void* const* d_in, const int* in_sizes, int n_in,
                              void* d_out, int out_size) {
    const float* x     = (const float*)d_in[0];
    const int*   xlen  = (const int*)d_in[1];
    const float* Wih1f = (const float*)d_in[2];
    const float* Whh1f = (const float*)d_in[3];
    const float* b1f   = (const float*)d_in[4];
    const float* Wih1b = (const float*)d_in[5];
    const float* Whh1b = (const float*)d_in[6];
    const float* b1b   = (const float*)d_in[7];
    const float* Wih2f = (const float*)d_in[8];
    const float* Whh2f = (const float*)d_in[9];
    const float* b2f   = (const float*)d_in[10];
    const float* Wih2b = (const float*)d_in[11];
    const float* Whh2b = (const float*)d_in[12];
    const float* b2b   = (const float*)d_in[13];
    const float* Wlin  = (const float*)d_in[14];
    const float* blin  = (const float*)d_in[15];
    float* out = (float*)d_out;

    static bool s_attr_done = false;
    if (!s_attr_done) {
        cudaFuncSetAttribute(k_lstm, cudaFuncAttributeMaxDynamicSharedMemorySize, LSTM_SMEM);
        cudaFuncSetAttribute(k_lstm, cudaFuncAttributeNonPortableClusterSizeAllowed, 1);
        s_attr_done = true;
    }

    float *xg1f, *xg1b, *xg2f, *xg2b, *out1, *pool1, *out2;
    cudaGetSymbolAddress((void**)&xg1f,  g_xg1f);
    cudaGetSymbolAddress((void**)&xg1b,  g_xg1b);
    cudaGetSymbolAddress((void**)&xg2f,  g_xg2f);
    cudaGetSymbolAddress((void**)&xg2b,  g_xg2b);
    cudaGetSymbolAddress((void**)&out1,  g_out1);
    cudaGetSymbolAddress((void**)&pool1, g_pool1);
    cudaGetSymbolAddress((void**)&out2,  g_out2);

    const long long ot_xg = (long long)G4H * NB;
    const long long or_xg = NB;
    const long long ob_xg = 1;

    // zero masked-output buffers (graph replays must rewrite every call)
    k_zero<<<4096, 256>>>(out1, (size_t)NB * T1 * HDC);
    k_zero<<<4096, 256>>>(out2, (size_t)NB * T2 * HDC);

    // layer-1 gate projections: M=1024, N=(2000 t x 32 b), K=80
    k_proj<<<dim3(G4H / 256, T1), 128>>>(x, Wih1f, b1f, xg1f, T1, D1, ot_xg, or_xg, ob_xg);
    k_proj<<<dim3(G4H / 256, T1), 128>>>(x, Wih1b, b1b, xg1b, T1, D1, ot_xg, or_xg, ob_xg);

    // cluster launch helper
    auto launch_lstm = [&](const float* xf, const float* xb,
                           const float* wf, const float* wb,
                           int shift, float* o, int Tt) {
        cudaLaunchConfig_t cfg = {};
        cfg.gridDim  = dim3(128, 1, 1);
        cfg.blockDim = dim3(256, 1, 1);
        cfg.dynamicSmemBytes = LSTM_SMEM;
        cfg.stream = 0;
        cudaLaunchAttribute attrs[1];
        attrs[0].id = cudaLaunchAttributeClusterDimension;
        attrs[0].val.clusterDim.x = CLSZ;
        attrs[0].val.clusterDim.y = 1;
        attrs[0].val.clusterDim.z = 1;
        cfg.attrs = attrs;
        cfg.numAttrs = 1;
        cudaLaunchKernelEx(&cfg, k_lstm, xf, xb, wf, wb, xlen, shift, o, Tt);
    };

    // layer-1 recurrence
    launch_lstm(xg1f, xg1b, Whh1f, Whh1b, 0, out1, T1);

    // max-pool stride 2
    k_pool<<<2048, 256>>>(out1, pool1);

    // layer-2 gate projections: M=1024, K=512
    k_proj<<<dim3(G4H / 256, T2), 128>>>(pool1, Wih2f, b2f, xg2f, T2, HDC, ot_xg, or_xg, ob_xg);
    k_proj<<<dim3(G4H / 256, T2), 128>>>(pool1, Wih2b, b2b, xg2b, T2, HDC, ot_xg, or_xg, ob_xg);

    // layer-2 recurrence (lengths = x_len >> 1)
    launch_lstm(xg2f, xg2b, Whh2f, Whh2b, 1, out2, T2);

    // final linear: out[b][t][o] -> M=512, K=512, store-along-row mode
    k_proj<<<dim3(OUTC / 256, T2), 128>>>(out2, Wlin, blin, out, T2, HDC,
                                          (long long)OUTC, 1LL, (long long)T2 * OUTC);

    // lens = x_len // 2 appended as float
    if (out_size > NB * T2 * OUTC) {
        k_lens<<<1, 32>>>(xlen, out + (size_t)NB * T2 * OUTC);
    }
}

// round 14
// speedup vs baseline: 1.7741x; 1.7741x over previous
#include <cuda_runtime.h>
#include <cuda_bf16.h>
#include <cstdint>
#include <cstddef>
#include <math.h>

#define NB   32      // batch
#define T1   2000
#define T2   1000
#define D1   80
#define HH   256     // hidden per direction
#define G4H  1024    // 4*H gate rows
#define HDC  512
#define OUTC 512
#define CLSZ 16      // cluster size = blocks per group (h-shards)

typedef unsigned long long ull;

// ---------------- f32x2 packed-FMA helpers (Blackwell FFMA2) -----------------
__device__ __forceinline__ void fma2(ull& d, ull a, ull b) {
    asm("fma.rn.f32x2 %0, %1, %2, %3;" : "=l"(d) : "l"(a), "l"(b), "l"(d));
}
__device__ __forceinline__ ull dup2(float x) {
    ull r; asm("mov.b64 %0, {%1, %1};" : "=l"(r) : "f"(x)); return r;
}
__device__ __forceinline__ float2 unp2(ull v) {
    float2 r; asm("mov.b64 {%0, %1}, %2;" : "=f"(r.x), "=f"(r.y) : "l"(v)); return r;
}
__device__ __forceinline__ uint32_t smem_u32(const void* p) {
    uint32_t a;
    asm("{ .reg .u64 t; cvta.to.shared.u64 t, %1; cvt.u32.u64 %0, t; }" : "=r"(a) : "l"(p));
    return a;
}
__device__ __forceinline__ uint32_t mapa_u32(uint32_t addr, int rank) {
    uint32_t r;
    asm("mapa.shared::cluster.u32 %0, %1, %2;" : "=r"(r) : "r"(addr), "r"(rank));
    return r;
}

// ---------------- device scratch ---------------------------------------------
__device__ float g_xg1f[(size_t)T1 * G4H * NB];   // [t][gate_row][b]
__device__ float g_xg1b[(size_t)T1 * G4H * NB];
__device__ float g_xg2f[(size_t)T2 * G4H * NB];
__device__ float g_xg2b[(size_t)T2 * G4H * NB];
__device__ float g_out1[(size_t)NB * T1 * HDC];   // [b][t][ch]
__device__ float g_pool1[(size_t)NB * T2 * HDC];
__device__ float g_out2[(size_t)NB * T2 * HDC];

// ---------------- small helpers ---------------------------------------------
__global__ void k_zero(float* __restrict__ p, size_t n) {
    size_t i = (size_t)blockIdx.x * blockDim.x + threadIdx.x;
    size_t st = (size_t)gridDim.x * blockDim.x;
    for (; i < n; i += st) p[i] = 0.f;
}

__global__ void k_pool(const float* __restrict__ in, float* __restrict__ out) {
    size_t n = (size_t)NB * T2 * HDC;
    size_t i = (size_t)blockIdx.x * blockDim.x + threadIdx.x;
    size_t st = (size_t)gridDim.x * blockDim.x;
    for (; i < n; i += st) {
        int c  = (int)(i % HDC);
        size_t r = i / HDC;
        int tp = (int)(r % T2);
        int b  = (int)(r / T2);
        const float* p = in + ((size_t)b * T1 + 2 * (size_t)tp) * HDC + c;
        out[i] = fmaxf(p[0], p[HDC]);
    }
}

__global__ void k_lens(const int* __restrict__ xlen, float* __restrict__ out) {
    int i = threadIdx.x;
    if (i < NB) out[i] = (float)(xlen[i] >> 1);
}

// ---------------- projection / linear GEMM: 256 threads, 4x8 tile ------------
// C[row][b] at time t: bias[row] + sum_k W[row][k] * X[(b*Tt+t)*K + k]
// Block tile: 256 rows x (one t x 32 b). 256 threads, thread tile 4 rows x 8 b.
// Same smem + instruction mix per output as the proven R5 kernel, but twice the
// warps per SM (16) to hide the per-chunk __syncthreads + LDG latency.
__global__ void __launch_bounds__(256, 2) k_proj(
    const float* __restrict__ X, const float* __restrict__ W,
    const float* __restrict__ bias, float* __restrict__ out,
    int Tt, int K, long long ot, long long orr, long long ob)
{
    __shared__ __align__(16) float a_sh[16][256];
    __shared__ __align__(16) float b_sh[16][32];

    const int t    = blockIdx.y;
    const int row0 = blockIdx.x * 256;
    const int tid  = threadIdx.x;
    const int rowg = tid >> 2;   // 0..63 -> rows rowg*4 .. +3
    const int colg = tid & 3;    // 0..3  -> b colg*8 .. +7

    ull acc[2][8];               // [row-pair(2)][col(8)]
#pragma unroll
    for (int i = 0; i < 2; i++)
#pragma unroll
        for (int j = 0; j < 8; j++) acc[i][j] = 0ull;

    for (int k0 = 0; k0 < K; k0 += 16) {
        // stage W chunk: each thread loads its own row (256 rows), 16 k
        {
            const float* wp = W + (size_t)(row0 + tid) * K + k0;
            float4 v0 = ((const float4*)wp)[0];
            float4 v1 = ((const float4*)wp)[1];
            float4 v2 = ((const float4*)wp)[2];
            float4 v3 = ((const float4*)wp)[3];
            a_sh[ 0][tid] = v0.x; a_sh[ 1][tid] = v0.y; a_sh[ 2][tid] = v0.z; a_sh[ 3][tid] = v0.w;
            a_sh[ 4][tid] = v1.x; a_sh[ 5][tid] = v1.y; a_sh[ 6][tid] = v1.z; a_sh[ 7][tid] = v1.w;
            a_sh[ 8][tid] = v2.x; a_sh[ 9][tid] = v2.y; a_sh[10][tid] = v2.z; a_sh[11][tid] = v2.w;
            a_sh[12][tid] = v3.x; a_sh[13][tid] = v3.y; a_sh[14][tid] = v3.z; a_sh[15][tid] = v3.w;
        }
        // stage X chunk: 32 b x 16 k (threads 0-127)
        if (tid < 128) {
            const int bb = tid >> 2, ko = (tid & 3) * 4;
            const float* xp = X + ((size_t)bb * Tt + t) * K + k0 + ko;
            float4 u = *(const float4*)xp;
            b_sh[ko + 0][bb] = u.x; b_sh[ko + 1][bb] = u.y;
            b_sh[ko + 2][bb] = u.z; b_sh[ko + 3][bb] = u.w;
        }
        __syncthreads();
#pragma unroll
        for (int kk = 0; kk < 16; kk++) {
            ulonglong2 a01 = *(const ulonglong2*)&a_sh[kk][rowg * 4];  // 4 rows = 2 pairs
            float4 u0 = *(const float4*)&b_sh[kk][colg * 8];
            float4 u1 = *(const float4*)&b_sh[kk][colg * 8 + 4];
            ull b0 = dup2(u0.x), b1 = dup2(u0.y), b2 = dup2(u0.z), b3 = dup2(u0.w);
            ull b4 = dup2(u1.x), b5 = dup2(u1.y), b6 = dup2(u1.z), b7 = dup2(u1.w);
            fma2(acc[0][0], a01.x, b0); fma2(acc[0][1], a01.x, b1);
            fma2(acc[0][2], a01.x, b2); fma2(acc[0][3], a01.x, b3);
            fma2(acc[0][4], a01.x, b4); fma2(acc[0][5], a01.x, b5);
            fma2(acc[0][6], a01.x, b6); fma2(acc[0][7], a01.x, b7);
            fma2(acc[1][0], a01.y, b0); fma2(acc[1][1], a01.y, b1);
            fma2(acc[1][2], a01.y, b2); fma2(acc[1][3], a01.y, b3);
            fma2(acc[1][4], a01.y, b4); fma2(acc[1][5], a01.y, b5);
            fma2(acc[1][6], a01.y, b6); fma2(acc[1][7], a01.y, b7);
        }
        __syncthreads();
    }

    // epilogue: rows rowg*4 .. +3, cols colg*8 .. +7
    const int rbase = row0 + rowg * 4;
    float4 bv0 = *(const float4*)&bias[rbase];
    const float bv[4] = {bv0.x, bv0.y, bv0.z, bv0.w};

    if (ob == 1) {
        float* op = out + (size_t)t * ot + (size_t)rbase * orr + colg * 8;
#pragma unroll
        for (int rp = 0; rp < 2; rp++) {
            float va[8], vb[8];
#pragma unroll
            for (int c = 0; c < 8; c++) {
                float2 u = unp2(acc[rp][c]);
                va[c] = u.x + bv[2 * rp];
                vb[c] = u.y + bv[2 * rp + 1];
            }
            float* r0 = op + (size_t)(2 * rp) * orr;
            float* r1 = op + (size_t)(2 * rp + 1) * orr;
            *(float4*)r0       = make_float4(va[0], va[1], va[2], va[3]);
            *(float4*)(r0 + 4) = make_float4(va[4], va[5], va[6], va[7]);
            *(float4*)r1       = make_float4(vb[0], vb[1], vb[2], vb[3]);
            *(float4*)(r1 + 4) = make_float4(vb[4], vb[5], vb[6], vb[7]);
        }
    } else {
        float* op = out + (size_t)t * ot + rbase;
#pragma unroll
        for (int c = 0; c < 8; c++) {
            size_t boff = (size_t)(colg * 8 + c) * ob;
            float2 p0 = unp2(acc[0][c]);
            float2 p1 = unp2(acc[1][c]);
            *(float4*)(op + boff) = make_float4(p0.x + bv[0], p0.y + bv[1],
                                                p1.x + bv[2], p1.y + bv[3]);
        }
    }
}

// ---------------- persistent recurrent LSTM (R12 verbatim — best known) ------
__device__ __forceinline__ float fsig(float x) {
    return 1.f / (1.f + __expf(-x));
}
__device__ __forceinline__ float ftanh(float x) {
    float e = __expf(2.f * x);
    return 1.f - 2.f / (e + 1.f);
}

// smem: w_sh 64KB [256][64] | h_sh 16KB [2][256][8] | part [8][64][9]
#define PART_STRIDE 9
#define HBUF_FLOATS (HH * 8)
#define HBUF_BYTES  (HBUF_FLOATS * 4)
#define OFF_HSH   65536
#define OFF_PART  (OFF_HSH + 2 * HBUF_BYTES)
#define LSTM_SMEM (OFF_PART + 8 * 64 * PART_STRIDE * 4)

__global__ void __launch_bounds__(256, 1) k_lstm(
    const float* __restrict__ xgF, const float* __restrict__ xgB,
    const float* __restrict__ WhhF, const float* __restrict__ WhhB,
    const int* __restrict__ xlen, int lenShift,
    float* __restrict__ out, int Tt)
{
    extern __shared__ __align__(16) char dynsmem[];
    float* w_sh = (float*)dynsmem;                   // [256][64]
    float* h_sh = (float*)(dynsmem + OFF_HSH);       // [2][256][8]
    float* part = (float*)(dynsmem + OFF_PART);      // [8][64][9]

    const int bx  = (int)blockIdx.x;
    const int dir = bx >> 6;
    const int bs  = (bx >> 4) & 3;
    const int hs  = bx & 15;           // cluster rank

    const float* xg  = dir ? xgB : xgF;
    const float* Whh = dir ? WhhB : WhhF;

    const int tid  = threadIdx.x;
    const int warp = tid >> 5, lane = tid & 31;
    const int q    = lane & 15;        // row quad (4 rows = 2 f32x2 pairs)
    const int bg4  = lane >> 4;        // batch group of 4 (0,1)
    const int kbase = warp * 32;       // 32 k per warp (8 warps)

    // ---- zero h buffers (both parities) ----
    {
        float4* hz = (float4*)h_sh;
        for (int j = tid; j < 2 * HBUF_FLOATS / 4; j += 256)
            hz[j] = make_float4(0.f, 0.f, 0.f, 0.f);
    }

    // ---- stage Whh slice [256 k][64 local rows] ----
    {
        const int r  = tid & 63;
        const int ko = (tid >> 6) * 64;    // 4 groups x 64 k
        const int grow = (r >> 4) * HH + hs * 16 + (r & 15);
        const float* wp = Whh + (size_t)grow * HH + ko;
#pragma unroll
        for (int j = 0; j < 64; j += 4) {
            float4 v = *(const float4*)(wp + j);
            w_sh[(size_t)(ko + j + 0) * 64 + r] = v.x;
            w_sh[(size_t)(ko + j + 1) * 64 + r] = v.y;
            w_sh[(size_t)(ko + j + 2) * 64 + r] = v.z;
            w_sh[(size_t)(ko + j + 3) * 64 + r] = v.w;
        }
    }

    // ---- peer DSMEM addresses for the h scatter (threads 0-127 own values) --
    const uint32_t h_u32 = smem_u32(h_sh);
    uint32_t peer[CLSZ];
#pragma unroll
    for (int r = 0; r < CLSZ; r++) peer[r] = mapa_u32(h_u32, r);
    const uint32_t selfOff = ((uint32_t)(hs * 128 + tid)) * 4u;   // valid for tid<128

    // ---- pointwise role (threads 0-127) ----
    const int hl_p = (tid >> 3) & 15;
    const int bl_p = tid & 7;
    const int hk   = hs * 16 + hl_p;
    const int b_g  = bs * 8 + bl_p;
    const int len_b = xlen[b_g] >> lenShift;
    int gmax = 0;
#pragma unroll
    for (int j = 0; j < 8; j++) {
        int l = xlen[bs * 8 + j] >> lenShift;
        gmax = (l > gmax) ? l : gmax;
    }
    float c_st = 0.f, h_st = 0.f;

    __syncthreads();
    // all CTAs' h buffers zeroed before any peer writes
    asm volatile("barrier.cluster.arrive.aligned;" ::: "memory");
    asm volatile("barrier.cluster.wait.aligned;" ::: "memory");

    // gate-input prefetch for step 0 (owner threads only)
    float xg0 = 0.f, xg1 = 0.f, xg2 = 0.f, xg3 = 0.f;
    if (tid < 128) {
        int tx = dir ? (len_b - 1) : 0;
        if (tx < 0) tx = 0;
        const float* xp = xg + (size_t)tx * (G4H * NB) + (size_t)hk * NB + b_g;
        xg0 = __ldg(xp);
        xg1 = __ldg(xp + 256 * NB);
        xg2 = __ldg(xp + 512 * NB);
        xg3 = __ldg(xp + 768 * NB);
    }

    for (int s = 0; s < gmax; s++) {
        const int bufp = s & 1;

        // ---- GEMM slice from local h_sh[bufp]: 8 warps x 32 k ----
        ull acc[2][4] = {};
        const float* wq = w_sh + (size_t)kbase * 64 + q * 4;
        const float* hq = h_sh + (size_t)bufp * HBUF_FLOATS + (size_t)kbase * 8 + bg4 * 4;
#pragma unroll 16
        for (int k = 0; k < 32; k++) {
            ulonglong2 wv = *(const ulonglong2*)(wq + (size_t)k * 64);
            float4 hv = *(const float4*)(hq + (size_t)k * 8);
            ull h0 = dup2(hv.x), h1 = dup2(hv.y), h2 = dup2(hv.z), h3 = dup2(hv.w);
            fma2(acc[0][0], wv.x, h0); fma2(acc[0][1], wv.x, h1);
            fma2(acc[0][2], wv.x, h2); fma2(acc[0][3], wv.x, h3);
            fma2(acc[1][0], wv.y, h0); fma2(acc[1][1], wv.y, h1);
            fma2(acc[1][2], wv.y, h2); fma2(acc[1][3], wv.y, h3);
        }

        // ---- partials: part[warp][row(64)][b(8)] stride 9 ----
#pragma unroll
        for (int i = 0; i < 2; i++) {
#pragma unroll
            for (int j = 0; j < 4; j++) {
                float2 u = unp2(acc[i][j]);
                float* p0 = part + ((size_t)warp * 64 + q * 4 + 2 * i) * PART_STRIDE + bg4 * 4 + j;
                p0[0] = u.x;
                p0[PART_STRIDE] = u.y;
            }
        }
        __syncthreads();

        if (tid < 128) {
            // ---- reduce over 8 warps + pointwise for (hl_p, bl_p) ----
            float g0 = xg0, g1 = xg1, g2 = xg2, g3 = xg3;
#pragma unroll
            for (int w = 0; w < 8; w++) {
                const float* pr = part + (size_t)w * 64 * PART_STRIDE + bl_p;
                g0 += pr[(0  + hl_p) * PART_STRIDE];
                g1 += pr[(16 + hl_p) * PART_STRIDE];
                g2 += pr[(32 + hl_p) * PART_STRIDE];
                g3 += pr[(48 + hl_p) * PART_STRIDE];
            }
            float ig = fsig(g0);
            float fg = fsig(g1);
            float gg = ftanh(g2);
            float og = fsig(g3);
            float c_n = fg * c_st + ig * gg;
            float h_n = og * ftanh(c_n);
            if (s < len_b) {
                c_st = c_n; h_st = h_n;
                int t_o = dir ? (len_b - 1 - s) : s;
                out[((size_t)b_g * Tt + t_o) * HDC + dir * HH + hk] = h_n;
            }

            // ---- scatter h to all 16 CTAs' h_sh[bufp^1] via DSMEM ----
            const uint32_t off = (uint32_t)((bufp ^ 1) * HBUF_BYTES) + selfOff;
            const float hv = h_st;
#pragma unroll
            for (int r = 0; r < CLSZ; r++) {
                asm volatile("st.shared::cluster.f32 [%0], %1;"
                             :: "r"(peer[r] + off), "f"(hv) : "memory");
            }
        }

        // release my stores; overlap xg prefetch with peers finishing
        asm volatile("barrier.cluster.arrive.aligned;" ::: "memory");
        if (tid < 128) {
            int sn = s + 1;
            int tx = dir ? (len_b - 1 - sn) : sn;
            if (tx < 0) tx = 0;
            if (tx >= Tt) tx = Tt - 1;
            const float* xp = xg + (size_t)tx * (G4H * NB) + (size_t)hk * NB + b_g;
            xg0 = __ldg(xp);
            xg1 = __ldg(xp + 256 * NB);
            xg2 = __ldg(xp + 512 * NB);
            xg3 = __ldg(xp + 768 * NB);
        }
        asm volatile("barrier.cluster.wait.aligned;" ::: "memory");
    }
}

// ---------------- host orchestration ----------------------------------------
extern "C" void kernel_launch(void* const* d_in, const int* in_sizes, int n_in,
                              void* d_out, int out_size) {
    const float* x     = (const float*)d_in[0];
    const int*   xlen  = (const int*)d_in[1];
    const float* Wih1f = (const float*)d_in[2];
    const float* Whh1f = (const float*)d_in[3];
    const float* b1f   = (const float*)d_in[4];
    const float* Wih1b = (const float*)d_in[5];
    const float* Whh1b = (const float*)d_in[6];
    const float* b1b   = (const float*)d_in[7];
    const float* Wih2f = (const float*)d_in[8];
    const float* Whh2f = (const float*)d_in[9];
    const float* b2f   = (const float*)d_in[10];
    const float* Wih2b = (const float*)d_in[11];
    const float* Whh2b = (const float*)d_in[12];
    const float* b2b   = (const float*)d_in[13];
    const float* Wlin  = (const float*)d_in[14];
    const float* blin  = (const float*)d_in[15];
    float* out = (float*)d_out;

    static bool s_attr_done = false;
    if (!s_attr_done) {
        cudaFuncSetAttribute(k_lstm, cudaFuncAttributeMaxDynamicSharedMemorySize, LSTM_SMEM);
        cudaFuncSetAttribute(k_lstm, cudaFuncAttributeNonPortableClusterSizeAllowed, 1);
        s_attr_done = true;
    }

    float *xg1f, *xg1b, *xg2f, *xg2b, *out1, *pool1, *out2;
    cudaGetSymbolAddress((void**)&xg1f,  g_xg1f);
    cudaGetSymbolAddress((void**)&xg1b,  g_xg1b);
    cudaGetSymbolAddress((void**)&xg2f,  g_xg2f);
    cudaGetSymbolAddress((void**)&xg2b,  g_xg2b);
    cudaGetSymbolAddress((void**)&out1,  g_out1);
    cudaGetSymbolAddress((void**)&pool1, g_pool1);
    cudaGetSymbolAddress((void**)&out2,  g_out2);

    const long long ot_xg = (long long)G4H * NB;
    const long long or_xg = NB;
    const long long ob_xg = 1;

    // zero masked-output buffers (graph replays must rewrite every call)
    k_zero<<<4096, 256>>>(out1, (size_t)NB * T1 * HDC);
    k_zero<<<4096, 256>>>(out2, (size_t)NB * T2 * HDC);

    // layer-1 gate projections: M=1024, N=(2000 t x 32 b), K=80
    k_proj<<<dim3(G4H / 256, T1), 256>>>(x, Wih1f, b1f, xg1f, T1, D1, ot_xg, or_xg, ob_xg);
    k_proj<<<dim3(G4H / 256, T1), 256>>>(x, Wih1b, b1b, xg1b, T1, D1, ot_xg, or_xg, ob_xg);

    // cluster launch helper
    auto launch_lstm = [&](const float* xf, const float* xb,
                           const float* wf, const float* wb,
                           int shift, float* o, int Tt) {
        cudaLaunchConfig_t cfg = {};
        cfg.gridDim  = dim3(128, 1, 1);
        cfg.blockDim = dim3(256, 1, 1);
        cfg.dynamicSmemBytes = LSTM_SMEM;
        cfg.stream = 0;
        cudaLaunchAttribute attrs[1];
        attrs[0].id = cudaLaunchAttributeClusterDimension;
        attrs[0].val.clusterDim.x = CLSZ;
        attrs[0].val.clusterDim.y = 1;
        attrs[0].val.clusterDim.z = 1;
        cfg.attrs = attrs;
        cfg.numAttrs = 1;
        cudaLaunchKernelEx(&cfg, k_lstm, xf, xb, wf, wb, xlen, shift, o, Tt);
    };

    // layer-1 recurrence
    launch_lstm(xg1f, xg1b, Whh1f, Whh1b, 0, out1, T1);

    // max-pool stride 2
    k_pool<<<2048, 256>>>(out1, pool1);

    // layer-2 gate projections: M=1024, K=512
    k_proj<<<dim3(G4H / 256, T2), 256>>>(pool1, Wih2f, b2f, xg2f, T2, HDC, ot_xg, or_xg, ob_xg);
    k_proj<<<dim3(G4H / 256, T2), 256>>>(pool1, Wih2b, b2b, xg2b, T2, HDC, ot_xg, or_xg, ob_xg);

    // layer-2 recurrence (lengths = x_len >> 1)
    launch_lstm(xg2f, xg2b, Whh2f, Whh2b, 1, out2, T2);

    // final linear: out[b][t][o] -> M=512, K=512, store-along-row mode
    k_proj<<<dim3(OUTC / 256, T2), 256>>>(out2, Wlin, blin, out, T2, HDC,
                                          (long long)OUTC, 1LL, (long long)T2 * OUTC);

    // lens = x_len // 2 appended as float
    if (out_size > NB * T2 * OUTC) {
        k_lens<<<1, 32>>>(xlen, out + (size_t)NB * T2 * OUTC);
    }
}

// round 15
// speedup vs baseline: 1.7976x; 1.0132x over previous
#include <cuda_runtime.h>
#include <cuda_bf16.h>
#include <cstdint>
#include <cstddef>
#include <math.h>

#define NB   32      // batch
#define T1   2000
#define T2   1000
#define D1   80
#define HH   256     // hidden per direction
#define G4H  1024    // 4*H gate rows
#define HDC  512
#define OUTC 512
#define CLSZ 8       // cluster size = h-shards (32 h each)

typedef unsigned long long ull;

// ---------------- f32x2 packed-FMA helpers (Blackwell FFMA2) -----------------
__device__ __forceinline__ void fma2(ull& d, ull a, ull b) {
    asm("fma.rn.f32x2 %0, %1, %2, %3;" : "=l"(d) : "l"(a), "l"(b), "l"(d));
}
__device__ __forceinline__ ull dup2(float x) {
    ull r; asm("mov.b64 %0, {%1, %1};" : "=l"(r) : "f"(x)); return r;
}
__device__ __forceinline__ float2 unp2(ull v) {
    float2 r; asm("mov.b64 {%0, %1}, %2;" : "=f"(r.x), "=f"(r.y) : "l"(v)); return r;
}
__device__ __forceinline__ uint32_t smem_u32(const void* p) {
    uint32_t a;
    asm("{ .reg .u64 t; cvta.to.shared.u64 t, %1; cvt.u32.u64 %0, t; }" : "=r"(a) : "l"(p));
    return a;
}
__device__ __forceinline__ uint32_t mapa_u32(uint32_t addr, int rank) {
    uint32_t r;
    asm("mapa.shared::cluster.u32 %0, %1, %2;" : "=r"(r) : "r"(addr), "r"(rank));
    return r;
}

// ---------------- device scratch ---------------------------------------------
__device__ float g_xg1f[(size_t)T1 * G4H * NB];   // [t][gate_row][b]
__device__ float g_xg1b[(size_t)T1 * G4H * NB];
__device__ float g_xg2f[(size_t)T2 * G4H * NB];
__device__ float g_xg2b[(size_t)T2 * G4H * NB];
__device__ float g_out1[(size_t)NB * T1 * HDC];   // [b][t][ch]
__device__ float g_pool1[(size_t)NB * T2 * HDC];
__device__ float g_out2[(size_t)NB * T2 * HDC];

// ---------------- small helpers ---------------------------------------------
__global__ void k_zero(float* __restrict__ p, size_t n) {
    size_t i = (size_t)blockIdx.x * blockDim.x + threadIdx.x;
    size_t st = (size_t)gridDim.x * blockDim.x;
    for (; i < n; i += st) p[i] = 0.f;
}

__global__ void k_pool(const float* __restrict__ in, float* __restrict__ out) {
    size_t n = (size_t)NB * T2 * HDC;
    size_t i = (size_t)blockIdx.x * blockDim.x + threadIdx.x;
    size_t st = (size_t)gridDim.x * blockDim.x;
    for (; i < n; i += st) {
        int c  = (int)(i % HDC);
        size_t r = i / HDC;
        int tp = (int)(r % T2);
        int b  = (int)(r / T2);
        const float* p = in + ((size_t)b * T1 + 2 * (size_t)tp) * HDC + c;
        out[i] = fmaxf(p[0], p[HDC]);
    }
}

__global__ void k_lens(const int* __restrict__ xlen, float* __restrict__ out) {
    int i = threadIdx.x;
    if (i < NB) out[i] = (float)(xlen[i] >> 1);
}

// ---------------- projection / linear GEMM (R5 version — proven, FROZEN) -----
__global__ void __launch_bounds__(128, 2) k_proj(
    const float* __restrict__ X, const float* __restrict__ W,
    const float* __restrict__ bias, float* __restrict__ out,
    int Tt, int K, long long ot, long long orr, long long ob)
{
    __shared__ __align__(16) float a_sh[16][256];
    __shared__ __align__(16) float b_sh[16][32];

    const int t    = blockIdx.y;
    const int row0 = blockIdx.x * 256;
    const int tid  = threadIdx.x;
    const int rowg = tid >> 2;
    const int colg = tid & 3;

    ull acc[4][8];
#pragma unroll
    for (int i = 0; i < 4; i++)
#pragma unroll
        for (int j = 0; j < 8; j++) acc[i][j] = 0ull;

    for (int k0 = 0; k0 < K; k0 += 16) {
        {
            const float* wp = W + (size_t)(row0 + tid) * K + k0;
            float4 v0 = ((const float4*)wp)[0];
            float4 v1 = ((const float4*)wp)[1];
            float4 v2 = ((const float4*)wp)[2];
            float4 v3 = ((const float4*)wp)[3];
            a_sh[ 0][tid] = v0.x; a_sh[ 1][tid] = v0.y; a_sh[ 2][tid] = v0.z; a_sh[ 3][tid] = v0.w;
            a_sh[ 4][tid] = v1.x; a_sh[ 5][tid] = v1.y; a_sh[ 6][tid] = v1.z; a_sh[ 7][tid] = v1.w;
            a_sh[ 8][tid] = v2.x; a_sh[ 9][tid] = v2.y; a_sh[10][tid] = v2.z; a_sh[11][tid] = v2.w;
            a_sh[12][tid] = v3.x; a_sh[13][tid] = v3.y; a_sh[14][tid] = v3.z; a_sh[15][tid] = v3.w;
            wp += (size_t)128 * K;
            v0 = ((const float4*)wp)[0];
            v1 = ((const float4*)wp)[1];
            v2 = ((const float4*)wp)[2];
            v3 = ((const float4*)wp)[3];
            const int r2 = tid + 128;
            a_sh[ 0][r2] = v0.x; a_sh[ 1][r2] = v0.y; a_sh[ 2][r2] = v0.z; a_sh[ 3][r2] = v0.w;
            a_sh[ 4][r2] = v1.x; a_sh[ 5][r2] = v1.y; a_sh[ 6][r2] = v1.z; a_sh[ 7][r2] = v1.w;
            a_sh[ 8][r2] = v2.x; a_sh[ 9][r2] = v2.y; a_sh[10][r2] = v2.z; a_sh[11][r2] = v2.w;
            a_sh[12][r2] = v3.x; a_sh[13][r2] = v3.y; a_sh[14][r2] = v3.z; a_sh[15][r2] = v3.w;
        }
        {
            const int bb = tid >> 2, ko = (tid & 3) * 4;
            const float* xp = X + ((size_t)bb * Tt + t) * K + k0 + ko;
            float4 u = *(const float4*)xp;
            b_sh[ko + 0][bb] = u.x; b_sh[ko + 1][bb] = u.y;
            b_sh[ko + 2][bb] = u.z; b_sh[ko + 3][bb] = u.w;
        }
        __syncthreads();
#pragma unroll
        for (int kk = 0; kk < 16; kk++) {
            ulonglong2 a01 = *(const ulonglong2*)&a_sh[kk][rowg * 8];
            ulonglong2 a23 = *(const ulonglong2*)&a_sh[kk][rowg * 8 + 4];
            float4 u0 = *(const float4*)&b_sh[kk][colg * 8];
            float4 u1 = *(const float4*)&b_sh[kk][colg * 8 + 4];
            ull b0 = dup2(u0.x), b1 = dup2(u0.y), b2 = dup2(u0.z), b3 = dup2(u0.w);
            ull b4 = dup2(u1.x), b5 = dup2(u1.y), b6 = dup2(u1.z), b7 = dup2(u1.w);
            fma2(acc[0][0], a01.x, b0); fma2(acc[0][1], a01.x, b1);
            fma2(acc[0][2], a01.x, b2); fma2(acc[0][3], a01.x, b3);
            fma2(acc[0][4], a01.x, b4); fma2(acc[0][5], a01.x, b5);
            fma2(acc[0][6], a01.x, b6); fma2(acc[0][7], a01.x, b7);
            fma2(acc[1][0], a01.y, b0); fma2(acc[1][1], a01.y, b1);
            fma2(acc[1][2], a01.y, b2); fma2(acc[1][3], a01.y, b3);
            fma2(acc[1][4], a01.y, b4); fma2(acc[1][5], a01.y, b5);
            fma2(acc[1][6], a01.y, b6); fma2(acc[1][7], a01.y, b7);
            fma2(acc[2][0], a23.x, b0); fma2(acc[2][1], a23.x, b1);
            fma2(acc[2][2], a23.x, b2); fma2(acc[2][3], a23.x, b3);
            fma2(acc[2][4], a23.x, b4); fma2(acc[2][5], a23.x, b5);
            fma2(acc[2][6], a23.x, b6); fma2(acc[2][7], a23.x, b7);
            fma2(acc[3][0], a23.y, b0); fma2(acc[3][1], a23.y, b1);
            fma2(acc[3][2], a23.y, b2); fma2(acc[3][3], a23.y, b3);
            fma2(acc[3][4], a23.y, b4); fma2(acc[3][5], a23.y, b5);
            fma2(acc[3][6], a23.y, b6); fma2(acc[3][7], a23.y, b7);
        }
        __syncthreads();
    }

    const int rbase = row0 + rowg * 8;
    float4 bv0 = *(const float4*)&bias[rbase];
    float4 bv1 = *(const float4*)&bias[rbase + 4];
    const float bv[8] = {bv0.x, bv0.y, bv0.z, bv0.w, bv1.x, bv1.y, bv1.z, bv1.w};

    if (ob == 1) {
        float* op = out + (size_t)t * ot + (size_t)rbase * orr + colg * 8;
#pragma unroll
        for (int rp = 0; rp < 4; rp++) {
            float va[8], vb[8];
#pragma unroll
            for (int c = 0; c < 8; c++) {
                float2 u = unp2(acc[rp][c]);
                va[c] = u.x + bv[2 * rp];
                vb[c] = u.y + bv[2 * rp + 1];
            }
            float* r0 = op + (size_t)(2 * rp) * orr;
            float* r1 = op + (size_t)(2 * rp + 1) * orr;
            *(float4*)r0       = make_float4(va[0], va[1], va[2], va[3]);
            *(float4*)(r0 + 4) = make_float4(va[4], va[5], va[6], va[7]);
            *(float4*)r1       = make_float4(vb[0], vb[1], vb[2], vb[3]);
            *(float4*)(r1 + 4) = make_float4(vb[4], vb[5], vb[6], vb[7]);
        }
    } else {
        float* op = out + (size_t)t * ot + rbase;
#pragma unroll
        for (int c = 0; c < 8; c++) {
            size_t boff = (size_t)(colg * 8 + c) * ob;
            float2 p0 = unp2(acc[0][c]);
            float2 p1 = unp2(acc[1][c]);
            float2 p2 = unp2(acc[2][c]);
            float2 p3 = unp2(acc[3][c]);
            *(float4*)(op + boff)     = make_float4(p0.x + bv[0], p0.y + bv[1], p1.x + bv[2], p1.y + bv[3]);
            *(float4*)(op + boff + 4) = make_float4(p2.x + bv[4], p2.y + bv[5], p3.x + bv[6], p3.y + bv[7]);
        }
    }
}

// ---------------- persistent recurrent LSTM: csz=8 clusters, 32h x 4b --------
__device__ __forceinline__ float fsig(float x) {
    return 1.f / (1.f + __expf(-x));
}
__device__ __forceinline__ float ftanh(float x) {
    float e = __expf(2.f * x);
    return 1.f - 2.f / (e + 1.f);
}

// smem: w_sh 128KB [256 k][128 rows] | h_sh 8KB [2][256 k][4 b] | part [8][128][5]
#define PART_STRIDE 5
#define HBUF_FLOATS (HH * 4)
#define HBUF_BYTES  (HBUF_FLOATS * 4)
#define OFF_HSH   131072
#define OFF_PART  (OFF_HSH + 2 * HBUF_BYTES)
#define LSTM_SMEM (OFF_PART + 8 * 128 * PART_STRIDE * 4)

__global__ void __launch_bounds__(256, 1) k_lstm(
    const float* __restrict__ xgF, const float* __restrict__ xgB,
    const float* __restrict__ WhhF, const float* __restrict__ WhhB,
    const int* __restrict__ xlen, int lenShift,
    float* __restrict__ out, int Tt)
{
    extern __shared__ __align__(16) char dynsmem[];
    float* w_sh = (float*)dynsmem;                   // [256 k][128 rows]
    float* h_sh = (float*)(dynsmem + OFF_HSH);       // [2][256][4]
    float* part = (float*)(dynsmem + OFF_PART);      // [8][128][5]

    const int bx  = (int)blockIdx.x;
    const int dir = bx >> 6;           // 0 fwd, 1 bwd
    const int bs  = (bx >> 3) & 7;     // batch shard (4 batches)
    const int hs  = bx & 7;            // cluster rank (32 h)

    const float* xg  = dir ? xgB : xgF;
    const float* Whh = dir ? WhhB : WhhF;

    const int tid  = threadIdx.x;
    const int warp = tid >> 5, lane = tid & 31;
    const int kbase = warp * 32;       // 32 k per warp (8 warps)

    // ---- zero h buffers (both parities) ----
    {
        float4* hz = (float4*)h_sh;
        for (int j = tid; j < 2 * HBUF_FLOATS / 4; j += 256)
            hz[j] = make_float4(0.f, 0.f, 0.f, 0.f);
    }

    // ---- stage Whh slice [256 k][128 local rows] ----
    // local row r: gate = r>>5, h_local = r&31 -> global row gate*256 + hs*32 + h_local
    {
        const int r  = tid & 127;
        const int ko = (tid >> 7) * 128;   // 2 k-halves
        const int grow = (r >> 5) * HH + hs * 32 + (r & 31);
        const float* wp = Whh + (size_t)grow * HH + ko;
#pragma unroll
        for (int j = 0; j < 128; j += 4) {
            float4 v = *(const float4*)(wp + j);
            w_sh[(size_t)(ko + j + 0) * 128 + r] = v.x;
            w_sh[(size_t)(ko + j + 1) * 128 + r] = v.y;
            w_sh[(size_t)(ko + j + 2) * 128 + r] = v.z;
            w_sh[(size_t)(ko + j + 3) * 128 + r] = v.w;
        }
    }

    // ---- peer DSMEM addresses for the h scatter (threads 0-127 own values) --
    const uint32_t h_u32 = smem_u32(h_sh);
    uint32_t peer[CLSZ];
#pragma unroll
    for (int r = 0; r < CLSZ; r++) peer[r] = mapa_u32(h_u32, r);
    // owner thread tid<128 holds (hl = tid>>2, bl = tid&3);
    // element index in buffer = hk*4 + bl = hs*128 + tid
    const uint32_t selfOff = ((uint32_t)(hs * 128 + tid)) * 4u;

    // ---- pointwise role (threads 0-127) ----
    const int hl_p = (tid >> 2) & 31;
    const int bl_p = tid & 3;
    const int hk   = hs * 32 + hl_p;
    const int b_g  = bs * 4 + bl_p;
    const int len_b = xlen[b_g] >> lenShift;
    int gmax = 0;
#pragma unroll
    for (int j = 0; j < 4; j++) {
        int l = xlen[bs * 4 + j] >> lenShift;
        gmax = (l > gmax) ? l : gmax;
    }
    float c_st = 0.f, h_st = 0.f;

    __syncthreads();
    // all CTAs' h buffers zeroed before any peer writes
    asm volatile("barrier.cluster.arrive.aligned;" ::: "memory");
    asm volatile("barrier.cluster.wait.aligned;" ::: "memory");

    // gate-input prefetch for step 0 (owner threads only)
    float xg0 = 0.f, xg1 = 0.f, xg2 = 0.f, xg3 = 0.f;
    if (tid < 128) {
        int tx = dir ? (len_b - 1) : 0;
        if (tx < 0) tx = 0;
        const float* xp = xg + (size_t)tx * (G4H * NB) + (size_t)hk * NB + b_g;
        xg0 = __ldg(xp);
        xg1 = __ldg(xp + 256 * NB);
        xg2 = __ldg(xp + 512 * NB);
        xg3 = __ldg(xp + 768 * NB);
    }

    for (int s = 0; s < gmax; s++) {
        const int bufp = s & 1;

        // ---- GEMM slice: 8 warps x 32 k; lane = rows lane*4..+3, 4 batches --
        ull acc[2][4] = {};
        const float* wq = w_sh + (size_t)kbase * 128 + lane * 4;
        const float* hq = h_sh + (size_t)bufp * HBUF_FLOATS + (size_t)kbase * 4;
#pragma unroll 16
        for (int k = 0; k < 32; k++) {
            ulonglong2 wv = *(const ulonglong2*)(wq + (size_t)k * 128); // rows as 2 f32x2 pairs
            float4 hv = *(const float4*)(hq + (size_t)k * 4);           // 4 batches (broadcast)
            ull h0 = dup2(hv.x), h1 = dup2(hv.y), h2 = dup2(hv.z), h3 = dup2(hv.w);
            fma2(acc[0][0], wv.x, h0); fma2(acc[0][1], wv.x, h1);
            fma2(acc[0][2], wv.x, h2); fma2(acc[0][3], wv.x, h3);
            fma2(acc[1][0], wv.y, h0); fma2(acc[1][1], wv.y, h1);
            fma2(acc[1][2], wv.y, h2); fma2(acc[1][3], wv.y, h3);
        }

        // ---- partials: part[warp][row(128)][b(4)] stride 5 ----
#pragma unroll
        for (int i = 0; i < 2; i++) {
            float2 u0 = unp2(acc[i][0]);
            float2 u1 = unp2(acc[i][1]);
            float2 u2 = unp2(acc[i][2]);
            float2 u3 = unp2(acc[i][3]);
            float* p0 = part + ((size_t)warp * 128 + lane * 4 + 2 * i) * PART_STRIDE;
            p0[0] = u0.x; p0[1] = u1.x; p0[2] = u2.x; p0[3] = u3.x;
            p0[PART_STRIDE + 0] = u0.y; p0[PART_STRIDE + 1] = u1.y;
            p0[PART_STRIDE + 2] = u2.y; p0[PART_STRIDE + 3] = u3.y;
        }
        __syncthreads();

        if (tid < 128) {
            // ---- reduce over 8 warps + pointwise for (hl_p, bl_p) ----
            float g0 = xg0, g1 = xg1, g2 = xg2, g3 = xg3;
#pragma unroll
            for (int w = 0; w < 8; w++) {
                const float* pr = part + (size_t)w * 128 * PART_STRIDE + bl_p;
                g0 += pr[(0  + hl_p) * PART_STRIDE];
                g1 += pr[(32 + hl_p) * PART_STRIDE];
                g2 += pr[(64 + hl_p) * PART_STRIDE];
                g3 += pr[(96 + hl_p) * PART_STRIDE];
            }
            float ig = fsig(g0);
            float fg = fsig(g1);
            float gg = ftanh(g2);
            float og = fsig(g3);
            float c_n = fg * c_st + ig * gg;
            float h_n = og * ftanh(c_n);
            if (s < len_b) {
                c_st = c_n; h_st = h_n;
                int t_o = dir ? (len_b - 1 - s) : s;
                out[((size_t)b_g * Tt + t_o) * HDC + dir * HH + hk] = h_n;
            }

            // ---- scatter h to all 8 CTAs' h_sh[bufp^1] via DSMEM ----
            const uint32_t off = (uint32_t)((bufp ^ 1) * HBUF_BYTES) + selfOff;
            const float hv = h_st;
#pragma unroll
            for (int r = 0; r < CLSZ; r++) {
                asm volatile("st.shared::cluster.f32 [%0], %1;"
                             :: "r"(peer[r] + off), "f"(hv) : "memory");
            }
        }

        // release my stores; overlap xg prefetch with peers finishing
        asm volatile("barrier.cluster.arrive.aligned;" ::: "memory");
        if (tid < 128) {
            int sn = s + 1;
            int tx = dir ? (len_b - 1 - sn) : sn;
            if (tx < 0) tx = 0;
            if (tx >= Tt) tx = Tt - 1;
            const float* xp = xg + (size_t)tx * (G4H * NB) + (size_t)hk * NB + b_g;
            xg0 = __ldg(xp);
            xg1 = __ldg(xp + 256 * NB);
            xg2 = __ldg(xp + 512 * NB);
            xg3 = __ldg(xp + 768 * NB);
        }
        asm volatile("barrier.cluster.wait.aligned;" ::: "memory");
    }
}

// ---------------- host orchestration ----------------------------------------
extern "C" void kernel_launch(void* const* d_in, const int* in_sizes, int n_in,
                              void* d_out, int out_size) {
    const float* x     = (const float*)d_in[0];
    const int*   xlen  = (const int*)d_in[1];
    const float* Wih1f = (const float*)d_in[2];
    const float* Whh1f = (const float*)d_in[3];
    const float* b1f   = (const float*)d_in[4];
    const float* Wih1b = (const float*)d_in[5];
    const float* Whh1b = (const float*)d_in[6];
    const float* b1b   = (const float*)d_in[7];
    const float* Wih2f = (const float*)d_in[8];
    const float* Whh2f = (const float*)d_in[9];
    const float* b2f   = (const float*)d_in[10];
    const float* Wih2b = (const float*)d_in[11];
    const float* Whh2b = (const float*)d_in[12];
    const float* b2b   = (const float*)d_in[13];
    const float* Wlin  = (const float*)d_in[14];
    const float* blin  = (const float*)d_in[15];
    float* out = (float*)d_out;

    static bool s_attr_done = false;
    if (!s_attr_done) {
        cudaFuncSetAttribute(k_lstm, cudaFuncAttributeMaxDynamicSharedMemorySize, LSTM_SMEM);
        s_attr_done = true;
    }

    float *xg1f, *xg1b, *xg2f, *xg2b, *out1, *pool1, *out2;
    cudaGetSymbolAddress((void**)&xg1f,  g_xg1f);
    cudaGetSymbolAddress((void**)&xg1b,  g_xg1b);
    cudaGetSymbolAddress((void**)&xg2f,  g_xg2f);
    cudaGetSymbolAddress((void**)&xg2b,  g_xg2b);
    cudaGetSymbolAddress((void**)&out1,  g_out1);
    cudaGetSymbolAddress((void**)&pool1, g_pool1);
    cudaGetSymbolAddress((void**)&out2,  g_out2);

    const long long ot_xg = (long long)G4H * NB;
    const long long or_xg = NB;
    const long long ob_xg = 1;

    // zero masked-output buffers (graph replays must rewrite every call)
    k_zero<<<4096, 256>>>(out1, (size_t)NB * T1 * HDC);
    k_zero<<<4096, 256>>>(out2, (size_t)NB * T2 * HDC);

    // layer-1 gate projections: M=1024, N=(2000 t x 32 b), K=80
    k_proj<<<dim3(G4H / 256, T1), 128>>>(x, Wih1f, b1f, xg1f, T1, D1, ot_xg, or_xg, ob_xg);
    k_proj<<<dim3(G4H / 256, T1), 128>>>(x, Wih1b, b1b, xg1b, T1, D1, ot_xg, or_xg, ob_xg);

    // cluster launch helper (clusterDim = 8, portable)
    auto launch_lstm = [&](const float* xf, const float* xb,
                           const float* wf, const float* wb,
                           int shift, float* o, int Tt) {
        cudaLaunchConfig_t cfg = {};
        cfg.gridDim  = dim3(128, 1, 1);
        cfg.blockDim = dim3(256, 1, 1);
        cfg.dynamicSmemBytes = LSTM_SMEM;
        cfg.stream = 0;
        cudaLaunchAttribute attrs[1];
        attrs[0].id = cudaLaunchAttributeClusterDimension;
        attrs[0].val.clusterDim.x = CLSZ;
        attrs[0].val.clusterDim.y = 1;
        attrs[0].val.clusterDim.z = 1;
        cfg.attrs = attrs;
        cfg.numAttrs = 1;
        cudaLaunchKernelEx(&cfg, k_lstm, xf, xb, wf, wb, xlen, shift, o, Tt);
    };

    // layer-1 recurrence
    launch_lstm(xg1f, xg1b, Whh1f, Whh1b, 0, out1, T1);

    // max-pool stride 2
    k_pool<<<2048, 256>>>(out1, pool1);

    // layer-2 gate projections: M=1024, K=512
    k_proj<<<dim3(G4H / 256, T2), 128>>>(pool1, Wih2f, b2f, xg2f, T2, HDC, ot_xg, or_xg, ob_xg);
    k_proj<<<dim3(G4H / 256, T2), 128>>>(pool1, Wih2b, b2b, xg2b, T2, HDC, ot_xg, or_xg, ob_xg);

    // layer-2 recurrence (lengths = x_len >> 1)
    launch_lstm(xg2f, xg2b, Whh2f, Whh2b, 1, out2, T2);

    // final linear: out[b][t][o] -> M=512, K=512, store-along-row mode
    k_proj<<<dim3(OUTC / 256, T2), 128>>>(out2, Wlin, blin, out, T2, HDC,
                                          (long long)OUTC, 1LL, (long long)T2 * OUTC);

    // lens = x_len // 2 appended as float
    if (out_size > NB * T2 * OUTC) {
        k_lens<<<1, 32>>>(xlen, out + (size_t)NB * T2 * OUTC);
    }
}

// round 16
// speedup vs baseline: 1.8694x; 1.0400x over previous
#include <cuda_runtime.h>
#include <cuda_bf16.h>
#include <cstdint>
#include <cstddef>
#include <math.h>

#define NB   32      // batch
#define T1   2000
#define T2   1000
#define D1   80
#define HH   256     // hidden per direction
#define G4H  1024    // 4*H gate rows
#define HDC  512
#define OUTC 512
#define CLSZ 16      // cluster size = blocks per group (h-shards)

typedef unsigned long long ull;

// ---------------- f32x2 packed-FMA helpers (Blackwell FFMA2) -----------------
__device__ __forceinline__ void fma2(ull& d, ull a, ull b) {
    asm("fma.rn.f32x2 %0, %1, %2, %3;" : "=l"(d) : "l"(a), "l"(b), "l"(d));
}
__device__ __forceinline__ ull dup2(float x) {
    ull r; asm("mov.b64 %0, {%1, %1};" : "=l"(r) : "f"(x)); return r;
}
__device__ __forceinline__ float2 unp2(ull v) {
    float2 r; asm("mov.b64 {%0, %1}, %2;" : "=f"(r.x), "=f"(r.y) : "l"(v)); return r;
}
__device__ __forceinline__ uint32_t smem_u32(const void* p) {
    uint32_t a;
    asm("{ .reg .u64 t; cvta.to.shared.u64 t, %1; cvt.u32.u64 %0, t; }" : "=r"(a) : "l"(p));
    return a;
}
__device__ __forceinline__ uint32_t mapa_u32(uint32_t addr, int rank) {
    uint32_t r;
    asm("mapa.shared::cluster.u32 %0, %1, %2;" : "=r"(r) : "r"(addr), "r"(rank));
    return r;
}

// ---------------- device scratch ---------------------------------------------
__device__ float g_xg1f[(size_t)T1 * G4H * NB];   // [t][gate_row][b]
__device__ float g_xg1b[(size_t)T1 * G4H * NB];
__device__ float g_xg2f[(size_t)T2 * G4H * NB];
__device__ float g_xg2b[(size_t)T2 * G4H * NB];
__device__ float g_out1[(size_t)NB * T1 * HDC];   // [b][t][ch]
__device__ float g_pool1[(size_t)NB * T2 * HDC];
__device__ float g_out2[(size_t)NB * T2 * HDC];

// ---------------- small helpers ---------------------------------------------
__global__ void k_zero(float* __restrict__ p, size_t n) {
    size_t i = (size_t)blockIdx.x * blockDim.x + threadIdx.x;
    size_t st = (size_t)gridDim.x * blockDim.x;
    for (; i < n; i += st) p[i] = 0.f;
}

__global__ void k_pool(const float* __restrict__ in, float* __restrict__ out) {
    size_t n = (size_t)NB * T2 * HDC;
    size_t i = (size_t)blockIdx.x * blockDim.x + threadIdx.x;
    size_t st = (size_t)gridDim.x * blockDim.x;
    for (; i < n; i += st) {
        int c  = (int)(i % HDC);
        size_t r = i / HDC;
        int tp = (int)(r % T2);
        int b  = (int)(r / T2);
        const float* p = in + ((size_t)b * T1 + 2 * (size_t)tp) * HDC + c;
        out[i] = fmaxf(p[0], p[HDC]);
    }
}

__global__ void k_lens(const int* __restrict__ xlen, float* __restrict__ out) {
    int i = threadIdx.x;
    if (i < NB) out[i] = (float)(xlen[i] >> 1);
}

// ---------------- projection / linear GEMM (R5 shape, 3 CTAs/SM) -------------
__global__ void __launch_bounds__(128, 3) k_proj(
    const float* __restrict__ X, const float* __restrict__ W,
    const float* __restrict__ bias, float* __restrict__ out,
    int Tt, int K, long long ot, long long orr, long long ob)
{
    __shared__ __align__(16) float a_sh[16][256];
    __shared__ __align__(16) float b_sh[16][32];

    const int t    = blockIdx.y;
    const int row0 = blockIdx.x * 256;
    const int tid  = threadIdx.x;
    const int rowg = tid >> 2;
    const int colg = tid & 3;

    ull acc[4][8];
#pragma unroll
    for (int i = 0; i < 4; i++)
#pragma unroll
        for (int j = 0; j < 8; j++) acc[i][j] = 0ull;

    for (int k0 = 0; k0 < K; k0 += 16) {
        {
            const float* wp = W + (size_t)(row0 + tid) * K + k0;
            float4 v0 = ((const float4*)wp)[0];
            float4 v1 = ((const float4*)wp)[1];
            float4 v2 = ((const float4*)wp)[2];
            float4 v3 = ((const float4*)wp)[3];
            a_sh[ 0][tid] = v0.x; a_sh[ 1][tid] = v0.y; a_sh[ 2][tid] = v0.z; a_sh[ 3][tid] = v0.w;
            a_sh[ 4][tid] = v1.x; a_sh[ 5][tid] = v1.y; a_sh[ 6][tid] = v1.z; a_sh[ 7][tid] = v1.w;
            a_sh[ 8][tid] = v2.x; a_sh[ 9][tid] = v2.y; a_sh[10][tid] = v2.z; a_sh[11][tid] = v2.w;
            a_sh[12][tid] = v3.x; a_sh[13][tid] = v3.y; a_sh[14][tid] = v3.z; a_sh[15][tid] = v3.w;
            wp += (size_t)128 * K;
            v0 = ((const float4*)wp)[0];
            v1 = ((const float4*)wp)[1];
            v2 = ((const float4*)wp)[2];
            v3 = ((const float4*)wp)[3];
            const int r2 = tid + 128;
            a_sh[ 0][r2] = v0.x; a_sh[ 1][r2] = v0.y; a_sh[ 2][r2] = v0.z; a_sh[ 3][r2] = v0.w;
            a_sh[ 4][r2] = v1.x; a_sh[ 5][r2] = v1.y; a_sh[ 6][r2] = v1.z; a_sh[ 7][r2] = v1.w;
            a_sh[ 8][r2] = v2.x; a_sh[ 9][r2] = v2.y; a_sh[10][r2] = v2.z; a_sh[11][r2] = v2.w;
            a_sh[12][r2] = v3.x; a_sh[13][r2] = v3.y; a_sh[14][r2] = v3.z; a_sh[15][r2] = v3.w;
        }
        {
            const int bb = tid >> 2, ko = (tid & 3) * 4;
            const float* xp = X + ((size_t)bb * Tt + t) * K + k0 + ko;
            float4 u = *(const float4*)xp;
            b_sh[ko + 0][bb] = u.x; b_sh[ko + 1][bb] = u.y;
            b_sh[ko + 2][bb] = u.z; b_sh[ko + 3][bb] = u.w;
        }
        __syncthreads();
#pragma unroll
        for (int kk = 0; kk < 16; kk++) {
            ulonglong2 a01 = *(const ulonglong2*)&a_sh[kk][rowg * 8];
            ulonglong2 a23 = *(const ulonglong2*)&a_sh[kk][rowg * 8 + 4];
            float4 u0 = *(const float4*)&b_sh[kk][colg * 8];
            float4 u1 = *(const float4*)&b_sh[kk][colg * 8 + 4];
            ull b0 = dup2(u0.x), b1 = dup2(u0.y), b2 = dup2(u0.z), b3 = dup2(u0.w);
            ull b4 = dup2(u1.x), b5 = dup2(u1.y), b6 = dup2(u1.z), b7 = dup2(u1.w);
            fma2(acc[0][0], a01.x, b0); fma2(acc[0][1], a01.x, b1);
            fma2(acc[0][2], a01.x, b2); fma2(acc[0][3], a01.x, b3);
            fma2(acc[0][4], a01.x, b4); fma2(acc[0][5], a01.x, b5);
            fma2(acc[0][6], a01.x, b6); fma2(acc[0][7], a01.x, b7);
            fma2(acc[1][0], a01.y, b0); fma2(acc[1][1], a01.y, b1);
            fma2(acc[1][2], a01.y, b2); fma2(acc[1][3], a01.y, b3);
            fma2(acc[1][4], a01.y, b4); fma2(acc[1][5], a01.y, b5);
            fma2(acc[1][6], a01.y, b6); fma2(acc[1][7], a01.y, b7);
            fma2(acc[2][0], a23.x, b0); fma2(acc[2][1], a23.x, b1);
            fma2(acc[2][2], a23.x, b2); fma2(acc[2][3], a23.x, b3);
            fma2(acc[2][4], a23.x, b4); fma2(acc[2][5], a23.x, b5);
            fma2(acc[2][6], a23.x, b6); fma2(acc[2][7], a23.x, b7);
            fma2(acc[3][0], a23.y, b0); fma2(acc[3][1], a23.y, b1);
            fma2(acc[3][2], a23.y, b2); fma2(acc[3][3], a23.y, b3);
            fma2(acc[3][4], a23.y, b4); fma2(acc[3][5], a23.y, b5);
            fma2(acc[3][6], a23.y, b6); fma2(acc[3][7], a23.y, b7);
        }
        __syncthreads();
    }

    const int rbase = row0 + rowg * 8;
    float4 bv0 = *(const float4*)&bias[rbase];
    float4 bv1 = *(const float4*)&bias[rbase + 4];
    const float bv[8] = {bv0.x, bv0.y, bv0.z, bv0.w, bv1.x, bv1.y, bv1.z, bv1.w};

    if (ob == 1) {
        float* op = out + (size_t)t * ot + (size_t)rbase * orr + colg * 8;
#pragma unroll
        for (int rp = 0; rp < 4; rp++) {
            float va[8], vb[8];
#pragma unroll
            for (int c = 0; c < 8; c++) {
                float2 u = unp2(acc[rp][c]);
                va[c] = u.x + bv[2 * rp];
                vb[c] = u.y + bv[2 * rp + 1];
            }
            float* r0 = op + (size_t)(2 * rp) * orr;
            float* r1 = op + (size_t)(2 * rp + 1) * orr;
            *(float4*)r0       = make_float4(va[0], va[1], va[2], va[3]);
            *(float4*)(r0 + 4) = make_float4(va[4], va[5], va[6], va[7]);
            *(float4*)r1       = make_float4(vb[0], vb[1], vb[2], vb[3]);
            *(float4*)(r1 + 4) = make_float4(vb[4], vb[5], vb[6], vb[7]);
        }
    } else {
        float* op = out + (size_t)t * ot + rbase;
#pragma unroll
        for (int c = 0; c < 8; c++) {
            size_t boff = (size_t)(colg * 8 + c) * ob;
            float2 p0 = unp2(acc[0][c]);
            float2 p1 = unp2(acc[1][c]);
            float2 p2 = unp2(acc[2][c]);
            float2 p3 = unp2(acc[3][c]);
            *(float4*)(op + boff)     = make_float4(p0.x + bv[0], p0.y + bv[1], p1.x + bv[2], p1.y + bv[3]);
            *(float4*)(op + boff + 4) = make_float4(p2.x + bv[4], p2.y + bv[5], p3.x + bv[6], p3.y + bv[7]);
        }
    }
}

// ---------------- persistent recurrent LSTM (R12 verbatim — best known) ------
__device__ __forceinline__ float fsig(float x) {
    return 1.f / (1.f + __expf(-x));
}
__device__ __forceinline__ float ftanh(float x) {
    float e = __expf(2.f * x);
    return 1.f - 2.f / (e + 1.f);
}

// smem: w_sh 64KB [256][64] | h_sh 16KB [2][256][8] | part [8][64][9]
#define PART_STRIDE 9
#define HBUF_FLOATS (HH * 8)
#define HBUF_BYTES  (HBUF_FLOATS * 4)
#define OFF_HSH   65536
#define OFF_PART  (OFF_HSH + 2 * HBUF_BYTES)
#define LSTM_SMEM (OFF_PART + 8 * 64 * PART_STRIDE * 4)

__global__ void __launch_bounds__(256, 1) k_lstm(
    const float* __restrict__ xgF, const float* __restrict__ xgB,
    const float* __restrict__ WhhF, const float* __restrict__ WhhB,
    const int* __restrict__ xlen, int lenShift,
    float* __restrict__ out, int Tt)
{
    extern __shared__ __align__(16) char dynsmem[];
    float* w_sh = (float*)dynsmem;                   // [256][64]
    float* h_sh = (float*)(dynsmem + OFF_HSH);       // [2][256][8]
    float* part = (float*)(dynsmem + OFF_PART);      // [8][64][9]

    const int bx  = (int)blockIdx.x;
    const int dir = bx >> 6;
    const int bs  = (bx >> 4) & 3;
    const int hs  = bx & 15;           // cluster rank

    const float* xg  = dir ? xgB : xgF;
    const float* Whh = dir ? WhhB : WhhF;

    const int tid  = threadIdx.x;
    const int warp = tid >> 5, lane = tid & 31;
    const int q    = lane & 15;        // row quad (4 rows = 2 f32x2 pairs)
    const int bg4  = lane >> 4;        // batch group of 4 (0,1)
    const int kbase = warp * 32;       // 32 k per warp (8 warps)

    // ---- zero h buffers (both parities) ----
    {
        float4* hz = (float4*)h_sh;
        for (int j = tid; j < 2 * HBUF_FLOATS / 4; j += 256)
            hz[j] = make_float4(0.f, 0.f, 0.f, 0.f);
    }

    // ---- stage Whh slice [256 k][64 local rows] ----
    {
        const int r  = tid & 63;
        const int ko = (tid >> 6) * 64;    // 4 groups x 64 k
        const int grow = (r >> 4) * HH + hs * 16 + (r & 15);
        const float* wp = Whh + (size_t)grow * HH + ko;
#pragma unroll
        for (int j = 0; j < 64; j += 4) {
            float4 v = *(const float4*)(wp + j);
            w_sh[(size_t)(ko + j + 0) * 64 + r] = v.x;
            w_sh[(size_t)(ko + j + 1) * 64 + r] = v.y;
            w_sh[(size_t)(ko + j + 2) * 64 + r] = v.z;
            w_sh[(size_t)(ko + j + 3) * 64 + r] = v.w;
        }
    }

    // ---- peer DSMEM addresses for the h scatter (threads 0-127 own values) --
    const uint32_t h_u32 = smem_u32(h_sh);
    uint32_t peer[CLSZ];
#pragma unroll
    for (int r = 0; r < CLSZ; r++) peer[r] = mapa_u32(h_u32, r);
    const uint32_t selfOff = ((uint32_t)(hs * 128 + tid)) * 4u;   // valid for tid<128

    // ---- pointwise role (threads 0-127) ----
    const int hl_p = (tid >> 3) & 15;
    const int bl_p = tid & 7;
    const int hk   = hs * 16 + hl_p;
    const int b_g  = bs * 8 + bl_p;
    const int len_b = xlen[b_g] >> lenShift;
    int gmax = 0;
#pragma unroll
    for (int j = 0; j < 8; j++) {
        int l = xlen[bs * 8 + j] >> lenShift;
        gmax = (l > gmax) ? l : gmax;
    }
    float c_st = 0.f, h_st = 0.f;

    __syncthreads();
    // all CTAs' h buffers zeroed before any peer writes
    asm volatile("barrier.cluster.arrive.aligned;" ::: "memory");
    asm volatile("barrier.cluster.wait.aligned;" ::: "memory");

    // gate-input prefetch for step 0 (owner threads only)
    float xg0 = 0.f, xg1 = 0.f, xg2 = 0.f, xg3 = 0.f;
    if (tid < 128) {
        int tx = dir ? (len_b - 1) : 0;
        if (tx < 0) tx = 0;
        const float* xp = xg + (size_t)tx * (G4H * NB) + (size_t)hk * NB + b_g;
        xg0 = __ldg(xp);
        xg1 = __ldg(xp + 256 * NB);
        xg2 = __ldg(xp + 512 * NB);
        xg3 = __ldg(xp + 768 * NB);
    }

    for (int s = 0; s < gmax; s++) {
        const int bufp = s & 1;

        // ---- GEMM slice from local h_sh[bufp]: 8 warps x 32 k ----
        ull acc[2][4] = {};
        const float* wq = w_sh + (size_t)kbase * 64 + q * 4;
        const float* hq = h_sh + (size_t)bufp * HBUF_FLOATS + (size_t)kbase * 8 + bg4 * 4;
#pragma unroll 16
        for (int k = 0; k < 32; k++) {
            ulonglong2 wv = *(const ulonglong2*)(wq + (size_t)k * 64);
            float4 hv = *(const float4*)(hq + (size_t)k * 8);
            ull h0 = dup2(hv.x), h1 = dup2(hv.y), h2 = dup2(hv.z), h3 = dup2(hv.w);
            fma2(acc[0][0], wv.x, h0); fma2(acc[0][1], wv.x, h1);
            fma2(acc[0][2], wv.x, h2); fma2(acc[0][3], wv.x, h3);
            fma2(acc[1][0], wv.y, h0); fma2(acc[1][1], wv.y, h1);
            fma2(acc[1][2], wv.y, h2); fma2(acc[1][3], wv.y, h3);
        }

        // ---- partials: part[warp][row(64)][b(8)] stride 9 ----
#pragma unroll
        for (int i = 0; i < 2; i++) {
#pragma unroll
            for (int j = 0; j < 4; j++) {
                float2 u = unp2(acc[i][j]);
                float* p0 = part + ((size_t)warp * 64 + q * 4 + 2 * i) * PART_STRIDE + bg4 * 4 + j;
                p0[0] = u.x;
                p0[PART_STRIDE] = u.y;
            }
        }
        __syncthreads();

        if (tid < 128) {
            // ---- reduce over 8 warps + pointwise for (hl_p, bl_p) ----
            float g0 = xg0, g1 = xg1, g2 = xg2, g3 = xg3;
#pragma unroll
            for (int w = 0; w < 8; w++) {
                const float* pr = part + (size_t)w * 64 * PART_STRIDE + bl_p;
                g0 += pr[(0  + hl_p) * PART_STRIDE];
                g1 += pr[(16 + hl_p) * PART_STRIDE];
                g2 += pr[(32 + hl_p) * PART_STRIDE];
                g3 += pr[(48 + hl_p) * PART_STRIDE];
            }
            float ig = fsig(g0);
            float fg = fsig(g1);
            float gg = ftanh(g2);
            float og = fsig(g3);
            float c_n = fg * c_st + ig * gg;
            float h_n = og * ftanh(c_n);
            if (s < len_b) {
                c_st = c_n; h_st = h_n;
                int t_o = dir ? (len_b - 1 - s) : s;
                out[((size_t)b_g * Tt + t_o) * HDC + dir * HH + hk] = h_n;
            }

            // ---- scatter h to all 16 CTAs' h_sh[bufp^1] via DSMEM ----
            const uint32_t off = (uint32_t)((bufp ^ 1) * HBUF_BYTES) + selfOff;
            const float hv = h_st;
#pragma unroll
            for (int r = 0; r < CLSZ; r++) {
                asm volatile("st.shared::cluster.f32 [%0], %1;"
                             :: "r"(peer[r] + off), "f"(hv) : "memory");
            }
        }

        // release my stores; overlap xg prefetch with peers finishing
        asm volatile("barrier.cluster.arrive.aligned;" ::: "memory");
        if (tid < 128) {
            int sn = s + 1;
            int tx = dir ? (len_b - 1 - sn) : sn;
            if (tx < 0) tx = 0;
            if (tx >= Tt) tx = Tt - 1;
            const float* xp = xg + (size_t)tx * (G4H * NB) + (size_t)hk * NB + b_g;
            xg0 = __ldg(xp);
            xg1 = __ldg(xp + 256 * NB);
            xg2 = __ldg(xp + 512 * NB);
            xg3 = __ldg(xp + 768 * NB);
        }
        asm volatile("barrier.cluster.wait.aligned;" ::: "memory");
    }
}

// ---------------- host orchestration ----------------------------------------
extern "C" void kernel_launch(void* const* d_in, const int* in_sizes, int n_in,
                              void* d_out, int out_size) {
    const float* x     = (const float*)d_in[0];
    const int*   xlen  = (const int*)d_in[1];
    const float* Wih1f = (const float*)d_in[2];
    const float* Whh1f = (const float*)d_in[3];
    const float* b1f   = (const float*)d_in[4];
    const float* Wih1b = (const float*)d_in[5];
    const float* Whh1b = (const float*)d_in[6];
    const float* b1b   = (const float*)d_in[7];
    const float* Wih2f = (const float*)d_in[8];
    const float* Whh2f = (const float*)d_in[9];
    const float* b2f   = (const float*)d_in[10];
    const float* Wih2b = (const float*)d_in[11];
    const float* Whh2b = (const float*)d_in[12];
    const float* b2b   = (const float*)d_in[13];
    const float* Wlin  = (const float*)d_in[14];
    const float* blin  = (const float*)d_in[15];
    float* out = (float*)d_out;

    static bool s_attr_done = false;
    if (!s_attr_done) {
        cudaFuncSetAttribute(k_lstm, cudaFuncAttributeMaxDynamicSharedMemorySize, LSTM_SMEM);
        cudaFuncSetAttribute(k_lstm, cudaFuncAttributeNonPortableClusterSizeAllowed, 1);
        s_attr_done = true;
    }

    float *xg1f, *xg1b, *xg2f, *xg2b, *out1, *pool1, *out2;
    cudaGetSymbolAddress((void**)&xg1f,  g_xg1f);
    cudaGetSymbolAddress((void**)&xg1b,  g_xg1b);
    cudaGetSymbolAddress((void**)&xg2f,  g_xg2f);
    cudaGetSymbolAddress((void**)&xg2b,  g_xg2b);
    cudaGetSymbolAddress((void**)&out1,  g_out1);
    cudaGetSymbolAddress((void**)&pool1, g_pool1);
    cudaGetSymbolAddress((void**)&out2,  g_out2);

    const long long ot_xg = (long long)G4H * NB;
    const long long or_xg = NB;
    const long long ob_xg = 1;

    // zero masked-output buffers (graph replays must rewrite every call)
    k_zero<<<4096, 256>>>(out1, (size_t)NB * T1 * HDC);
    k_zero<<<4096, 256>>>(out2, (size_t)NB * T2 * HDC);

    // layer-1 gate projections: M=1024, N=(2000 t x 32 b), K=80
    k_proj<<<dim3(G4H / 256, T1), 128>>>(x, Wih1f, b1f, xg1f, T1, D1, ot_xg, or_xg, ob_xg);
    k_proj<<<dim3(G4H / 256, T1), 128>>>(x, Wih1b, b1b, xg1b, T1, D1, ot_xg, or_xg, ob_xg);

    // cluster launch helper
    auto launch_lstm = [&](const float* xf, const float* xb,
                           const float* wf, const float* wb,
                           int shift, float* o, int Tt) {
        cudaLaunchConfig_t cfg = {};
        cfg.gridDim  = dim3(128, 1, 1);
        cfg.blockDim = dim3(256, 1, 1);
        cfg.dynamicSmemBytes = LSTM_SMEM;
        cfg.stream = 0;
        cudaLaunchAttribute attrs[1];
        attrs[0].id = cudaLaunchAttributeClusterDimension;
        attrs[0].val.clusterDim.x = CLSZ;
        attrs[0].val.clusterDim.y = 1;
        attrs[0].val.clusterDim.z = 1;
        cfg.attrs = attrs;
        cfg.numAttrs = 1;
        cudaLaunchKernelEx(&cfg, k_lstm, xf, xb, wf, wb, xlen, shift, o, Tt);
    };

    // layer-1 recurrence
    launch_lstm(xg1f, xg1b, Whh1f, Whh1b, 0, out1, T1);

    // max-pool stride 2
    k_pool<<<2048, 256>>>(out1, pool1);

    // layer-2 gate projections: M=1024, K=512
    k_proj<<<dim3(G4H / 256, T2), 128>>>(pool1, Wih2f, b2f, xg2f, T2, HDC, ot_xg, or_xg, ob_xg);
    k_proj<<<dim3(G4H / 256, T2), 128>>>(pool1, Wih2b, b2b, xg2b, T2, HDC, ot_xg, or_xg, ob_xg);

    // layer-2 recurrence (lengths = x_len >> 1)
    launch_lstm(xg2f, xg2b, Whh2f, Whh2b, 1, out2, T2);

    // final linear: out[b][t][o] -> M=512, K=512, store-along-row mode
    k_proj<<<dim3(OUTC / 256, T2), 128>>>(out2, Wlin, blin, out, T2, HDC,
                                          (long long)OUTC, 1LL, (long long)T2 * OUTC);

    // lens = x_len // 2 appended as float
    if (out_size > NB * T2 * OUTC) {
        k_lens<<<1, 32>>>(xlen, out + (size_t)NB * T2 * OUTC);
    }
}